// round 12
// baseline (speedup 1.0000x reference)
#include <cuda_runtime.h>

// ---------------------------------------------------------------------------
// SplitPool, round 11: 2-launch pipeline. Pool = warp-contiguous regions,
// 8-wide unconditional load batches (MLP=8), branch-free chunk-remainder
// handling (predicated parallel loads), pre-scaled atomicAdd into d_out.
// ---------------------------------------------------------------------------

#define DIM 128
#define DIM4 (DIM / 4)
#define MAX_CHUNKS 8192
#define MAX_B 64
#define BLOCKS_PER_SM 5
#define THREADS 256

__device__ int   g_cs[MAX_CHUNKS + 2];   // exclusive row offsets (chunk starts)
__device__ int   g_dest[MAX_CHUNKS + 1]; // output float offset, -1 = dropped
__device__ float g_inv[MAX_CHUNKS];      // 1 / max(count, 1)

// ---------------------------------------------------------------------------
// Kernel 1: setup. Block 0: scan + chunk metadata. Blocks >=1: zero output.
// ---------------------------------------------------------------------------
__global__ __launch_bounds__(1024) void setup_kernel(
    const int* __restrict__ cs, int n_chunks,
    const int* __restrict__ np, int B, int P,
    float* __restrict__ out, int out_f4) {

    if (blockIdx.x > 0) {
        float4* o4 = reinterpret_cast<float4*>(out);
        const float4 z = make_float4(0.f, 0.f, 0.f, 0.f);
        for (int i = (blockIdx.x - 1) * blockDim.x + threadIdx.x; i < out_f4;
             i += (gridDim.x - 1) * blockDim.x)
            o4[i] = z;
        return;
    }

    __shared__ int warp_pref[32];
    __shared__ int s_pool[MAX_B + 1];
    __shared__ int s_np[MAX_B];

    const int t = threadIdx.x;
    const int lane = t & 31;
    const int w = t >> 5;
    const int per = (n_chunks + 1023) >> 10;   // <= 8 for MAX_CHUNKS=8192

    int v[8];
    int tot = 0;
    #pragma unroll
    for (int k = 0; k < 8; k++) {
        int idx = t * per + k;
        int val = (k < per && idx < n_chunks) ? cs[idx] : 0;
        v[k] = val;
        tot += val;
    }

    // inclusive warp scan of per-thread totals
    int inc = tot;
    #pragma unroll
    for (int off = 1; off < 32; off <<= 1) {
        int n = __shfl_up_sync(0xffffffffu, inc, off);
        if (lane >= off) inc += n;
    }
    if (lane == 31) warp_pref[w] = inc;
    if (t < B) s_np[t] = np[t];
    __syncthreads();

    if (w == 0) {
        int ws = warp_pref[lane];
        #pragma unroll
        for (int off = 1; off < 32; off <<= 1) {
            int n = __shfl_up_sync(0xffffffffu, ws, off);
            if (lane >= off) ws += n;
        }
        warp_pref[lane] = ws;   // inclusive scan of warp sums
    }
    __syncthreads();

    int pref = inc - tot + (w > 0 ? warp_pref[w - 1] : 0);  // exclusive prefix
    #pragma unroll
    for (int k = 0; k < 8; k++) {
        int idx = t * per + k;
        if (k < per && idx < n_chunks) {
            g_cs[idx] = pref;
            pref += v[k];
        }
    }
    if (t == 1023) {
        g_cs[n_chunks] = warp_pref[31];
        g_cs[n_chunks + 1] = 0x7fffffff;   // sentinel
    }

    if (t == 0) {
        int acc = 0;
        for (int i = 0; i < B; i++) { s_pool[i] = acc; acc += s_np[i] + 1; }
        s_pool[B] = acc;
        g_dest[n_chunks] = -1;             // safe target for trailing flush
    }
    __syncthreads();

    // per-chunk destination + inverse count
    #pragma unroll
    for (int k = 0; k < 8; k++) {
        int c = t * per + k;
        if (k >= per || c >= n_chunks) break;
        int i = 0;
        while (i < B - 1 && s_pool[i + 1] <= c) i++;
        int peak = c - s_pool[i];
        bool valid = peak < s_np[i];
        g_dest[c] = valid ? (i * P + peak) * DIM : -1;
        g_inv[c]  = 1.0f / (float)max(v[k], 1);
    }
}

// ---------------------------------------------------------------------------
// Kernel 2: streaming segment reduction, MLP=8, branch-free boundaries.
// Each warp owns a contiguous row range. Interior 8-row batches issue 8
// back-to-back LDG.128 with no intervening control flow. A chunk remainder
// (<8 rows, all in one chunk) issues its loads predicated but in parallel.
// ---------------------------------------------------------------------------
__global__ __launch_bounds__(THREADS, BLOCKS_PER_SM)
void pool_kernel(const float* __restrict__ x, float* __restrict__ out,
                 int n_chunks, int total_rows, int rpw) {
    const int gw = (blockIdx.x * blockDim.x + threadIdx.x) >> 5;
    const int lane = threadIdx.x & 31;
    const int r0 = gw * rpw;
    if (r0 >= total_rows) return;
    const int r_end = min(r0 + rpw, total_rows);

    // binary search: largest chunk c with g_cs[c] <= r0
    int lo = 0, hi = n_chunks - 1;
    while (lo < hi) {
        int mid = (lo + hi + 1) >> 1;
        if (__ldg(&g_cs[mid]) <= r0) lo = mid; else hi = mid - 1;
    }
    int c = lo;
    int cend = __ldg(&g_cs[c + 1]);

    const float4* __restrict__ xv = reinterpret_cast<const float4*>(x);
    float4 acc = make_float4(0.f, 0.f, 0.f, 0.f);

    int r = r0;
    while (r < r_end) {
        const int lim = min(cend, r_end);

        // interior: full 8-row batches, zero control flow between loads
        while (r + 8 <= lim) {
            float4 v[8];
            const long long base = (long long)r * DIM4 + lane;
            #pragma unroll
            for (int k = 0; k < 8; k++)
                v[k] = __ldcs(xv + base + k * DIM4);
            #pragma unroll
            for (int k = 0; k < 8; k++) {
                acc.x += v[k].x; acc.y += v[k].y;
                acc.z += v[k].z; acc.w += v[k].w;
            }
            r += 8;
        }

        // remainder (< 8 rows, all in chunk c): predicated parallel loads
        const int rem = lim - r;
        if (rem > 0) {
            float4 v[7];
            const long long base = (long long)r * DIM4 + lane;
            #pragma unroll
            for (int k = 0; k < 7; k++)
                if (k < rem) v[k] = __ldcs(xv + base + k * DIM4);
            #pragma unroll
            for (int k = 0; k < 7; k++)
                if (k < rem) {
                    acc.x += v[k].x; acc.y += v[k].y;
                    acc.z += v[k].z; acc.w += v[k].w;
                }
            r = lim;
        }

        // chunk finished inside our region -> flush and advance
        if (r == cend) {
            const int dest = __ldg(&g_dest[c]);
            if (dest >= 0) {
                const float inv = __ldg(&g_inv[c]);
                float* o = out + dest + lane * 4;
                atomicAdd(o + 0, acc.x * inv);
                atomicAdd(o + 1, acc.y * inv);
                atomicAdd(o + 2, acc.z * inv);
                atomicAdd(o + 3, acc.w * inv);
            }
            acc = make_float4(0.f, 0.f, 0.f, 0.f);
            c++;
            cend = __ldg(&g_cs[c + 1]);
        }
    }

    // trailing partial for current chunk (g_dest[n_chunks] = -1 guards OOB)
    const int dest = __ldg(&g_dest[c]);
    if (dest >= 0) {
        const float inv = __ldg(&g_inv[c]);
        float* o = out + dest + lane * 4;
        atomicAdd(o + 0, acc.x * inv);
        atomicAdd(o + 1, acc.y * inv);
        atomicAdd(o + 2, acc.z * inv);
        atomicAdd(o + 3, acc.w * inv);
    }
}

// ---------------------------------------------------------------------------
// Launch
// ---------------------------------------------------------------------------
extern "C" void kernel_launch(void* const* d_in, const int* in_sizes, int n_in,
                              void* d_out, int out_size) {
    const float* x       = (const float*)d_in[0];
    const int*   cs      = (const int*)d_in[1];
    const int*   n_peaks = (const int*)d_in[2];

    const int n_chunks   = in_sizes[1];
    const int B          = in_sizes[2];
    const int total_rows = in_sizes[0] / DIM;
    const int P          = out_size / (B * DIM);   // max_n_peaks

    // 1. setup: block 0 scans + builds chunk metadata; blocks 1..64 zero out.
    setup_kernel<<<65, 1024>>>(cs, n_chunks, n_peaks, B, P,
                               (float*)d_out, out_size / 4);

    // 2. pool: single wave, one contiguous row range per warp.
    int sms = 148, dev = 0;
    cudaGetDevice(&dev);
    cudaDeviceGetAttribute(&sms, cudaDevAttrMultiProcessorCount, dev);
    const int nblk = sms * BLOCKS_PER_SM;
    const int n_warps = nblk * (THREADS / 32);
    const int rpw = (total_rows + n_warps - 1) / n_warps;
    pool_kernel<<<nblk, THREADS>>>(x, (float*)d_out, n_chunks, total_rows, rpw);
}

// round 13
// speedup vs baseline: 1.0292x; 1.0292x over previous
#include <cuda_runtime.h>

// ---------------------------------------------------------------------------
// SplitPool, round 12: 2-launch pipeline with PDL overlap.
//   1. setup_kernel : block 0 -> shfl-scan chunk_size, per-chunk dest slot +
//                     1/count; blocks 1..N -> zero d_out. Each block triggers
//                     programmatic launch completion when its writes are done.
//   2. pool_kernel  : launched with programmaticStreamSerialization; each
//                     block calls cudaGridDependencySynchronize() before
//                     consuming setup results. Warp-contiguous regions,
//                     8-wide unconditional load batches (MLP=8), pre-scaled
//                     atomicAdd straight into d_out. Pool is LTS-roofline
//                     bound (~5.35 TB/s); PDL shaves the launch gap.
// ---------------------------------------------------------------------------

#define DIM 128
#define DIM4 (DIM / 4)
#define MAX_CHUNKS 8192
#define MAX_B 64
#define BLOCKS_PER_SM 5
#define THREADS 256

__device__ int   g_cs[MAX_CHUNKS + 2];   // exclusive row offsets (chunk starts)
__device__ int   g_dest[MAX_CHUNKS + 1]; // output float offset, -1 = dropped
__device__ float g_inv[MAX_CHUNKS];      // 1 / max(count, 1)

// ---------------------------------------------------------------------------
// Kernel 1: setup. Block 0: scan + chunk metadata. Blocks >=1: zero output.
// ---------------------------------------------------------------------------
__global__ __launch_bounds__(1024) void setup_kernel(
    const int* __restrict__ cs, int n_chunks,
    const int* __restrict__ np, int B, int P,
    float* __restrict__ out, int out_f4) {

    if (blockIdx.x > 0) {
        float4* o4 = reinterpret_cast<float4*>(out);
        const float4 z = make_float4(0.f, 0.f, 0.f, 0.f);
        for (int i = (blockIdx.x - 1) * blockDim.x + threadIdx.x; i < out_f4;
             i += (gridDim.x - 1) * blockDim.x)
            o4[i] = z;
        cudaTriggerProgrammaticLaunchCompletion();
        return;
    }

    __shared__ int warp_pref[32];
    __shared__ int s_pool[MAX_B + 1];
    __shared__ int s_np[MAX_B];

    const int t = threadIdx.x;
    const int lane = t & 31;
    const int w = t >> 5;
    const int per = (n_chunks + 1023) >> 10;   // <= 8 for MAX_CHUNKS=8192

    int v[8];
    int tot = 0;
    #pragma unroll
    for (int k = 0; k < 8; k++) {
        int idx = t * per + k;
        int val = (k < per && idx < n_chunks) ? cs[idx] : 0;
        v[k] = val;
        tot += val;
    }

    // inclusive warp scan of per-thread totals
    int inc = tot;
    #pragma unroll
    for (int off = 1; off < 32; off <<= 1) {
        int n = __shfl_up_sync(0xffffffffu, inc, off);
        if (lane >= off) inc += n;
    }
    if (lane == 31) warp_pref[w] = inc;
    if (t < B) s_np[t] = np[t];
    __syncthreads();

    if (w == 0) {
        int ws = warp_pref[lane];
        #pragma unroll
        for (int off = 1; off < 32; off <<= 1) {
            int n = __shfl_up_sync(0xffffffffu, ws, off);
            if (lane >= off) ws += n;
        }
        warp_pref[lane] = ws;   // inclusive scan of warp sums
    }
    __syncthreads();

    int pref = inc - tot + (w > 0 ? warp_pref[w - 1] : 0);  // exclusive prefix
    #pragma unroll
    for (int k = 0; k < 8; k++) {
        int idx = t * per + k;
        if (k < per && idx < n_chunks) {
            g_cs[idx] = pref;
            pref += v[k];
        }
    }
    if (t == 1023) {
        g_cs[n_chunks] = warp_pref[31];
        g_cs[n_chunks + 1] = 0x7fffffff;   // sentinel
    }

    if (t == 0) {
        int acc = 0;
        for (int i = 0; i < B; i++) { s_pool[i] = acc; acc += s_np[i] + 1; }
        s_pool[B] = acc;
        g_dest[n_chunks] = -1;             // safe target for trailing flush
    }
    __syncthreads();

    // per-chunk destination + inverse count
    #pragma unroll
    for (int k = 0; k < 8; k++) {
        int c = t * per + k;
        if (k >= per || c >= n_chunks) break;
        int i = 0;
        while (i < B - 1 && s_pool[i + 1] <= c) i++;
        int peak = c - s_pool[i];
        bool valid = peak < s_np[i];
        g_dest[c] = valid ? (i * P + peak) * DIM : -1;
        g_inv[c]  = 1.0f / (float)max(v[k], 1);
    }
    cudaTriggerProgrammaticLaunchCompletion();
}

// ---------------------------------------------------------------------------
// Kernel 2: streaming segment reduction, MLP=8, branch-free boundaries.
// ---------------------------------------------------------------------------
__global__ __launch_bounds__(THREADS, BLOCKS_PER_SM)
void pool_kernel(const float* __restrict__ x, float* __restrict__ out,
                 int n_chunks, int total_rows, int rpw) {
    const int gw = (blockIdx.x * blockDim.x + threadIdx.x) >> 5;
    const int lane = threadIdx.x & 31;
    const int r0 = gw * rpw;

    // Wait for setup's writes (g_cs/g_dest/g_inv + zeroed d_out) to be visible.
    cudaGridDependencySynchronize();

    if (r0 >= total_rows) return;
    const int r_end = min(r0 + rpw, total_rows);

    // binary search: largest chunk c with g_cs[c] <= r0
    int lo = 0, hi = n_chunks - 1;
    while (lo < hi) {
        int mid = (lo + hi + 1) >> 1;
        if (__ldg(&g_cs[mid]) <= r0) lo = mid; else hi = mid - 1;
    }
    int c = lo;
    int cend = __ldg(&g_cs[c + 1]);

    const float4* __restrict__ xv = reinterpret_cast<const float4*>(x);
    float4 acc = make_float4(0.f, 0.f, 0.f, 0.f);

    int r = r0;
    while (r < r_end) {
        const int lim = min(cend, r_end);

        // interior: full 8-row batches, zero control flow between loads
        while (r + 8 <= lim) {
            float4 v[8];
            const long long base = (long long)r * DIM4 + lane;
            #pragma unroll
            for (int k = 0; k < 8; k++)
                v[k] = __ldcs(xv + base + k * DIM4);
            #pragma unroll
            for (int k = 0; k < 8; k++) {
                acc.x += v[k].x; acc.y += v[k].y;
                acc.z += v[k].z; acc.w += v[k].w;
            }
            r += 8;
        }

        // remainder (< 8 rows, all in chunk c): predicated parallel loads
        const int rem = lim - r;
        if (rem > 0) {
            float4 v[7];
            const long long base = (long long)r * DIM4 + lane;
            #pragma unroll
            for (int k = 0; k < 7; k++)
                if (k < rem) v[k] = __ldcs(xv + base + k * DIM4);
            #pragma unroll
            for (int k = 0; k < 7; k++)
                if (k < rem) {
                    acc.x += v[k].x; acc.y += v[k].y;
                    acc.z += v[k].z; acc.w += v[k].w;
                }
            r = lim;
        }

        // chunk finished inside our region -> flush and advance
        if (r == cend) {
            const int dest = __ldg(&g_dest[c]);
            if (dest >= 0) {
                const float inv = __ldg(&g_inv[c]);
                float* o = out + dest + lane * 4;
                atomicAdd(o + 0, acc.x * inv);
                atomicAdd(o + 1, acc.y * inv);
                atomicAdd(o + 2, acc.z * inv);
                atomicAdd(o + 3, acc.w * inv);
            }
            acc = make_float4(0.f, 0.f, 0.f, 0.f);
            c++;
            cend = __ldg(&g_cs[c + 1]);
        }
    }

    // trailing partial for current chunk (g_dest[n_chunks] = -1 guards OOB)
    const int dest = __ldg(&g_dest[c]);
    if (dest >= 0) {
        const float inv = __ldg(&g_inv[c]);
        float* o = out + dest + lane * 4;
        atomicAdd(o + 0, acc.x * inv);
        atomicAdd(o + 1, acc.y * inv);
        atomicAdd(o + 2, acc.z * inv);
        atomicAdd(o + 3, acc.w * inv);
    }
}

// ---------------------------------------------------------------------------
// Launch: setup, then pool with programmatic (PDL) dependency so the pool's
// launch latency overlaps setup execution.
// ---------------------------------------------------------------------------
extern "C" void kernel_launch(void* const* d_in, const int* in_sizes, int n_in,
                              void* d_out, int out_size) {
    const float* x       = (const float*)d_in[0];
    const int*   cs      = (const int*)d_in[1];
    const int*   n_peaks = (const int*)d_in[2];

    const int n_chunks   = in_sizes[1];
    const int B          = in_sizes[2];
    const int total_rows = in_sizes[0] / DIM;
    const int P          = out_size / (B * DIM);   // max_n_peaks

    // 1. setup: block 0 scans + builds chunk metadata; blocks 1..64 zero out.
    setup_kernel<<<65, 1024>>>(cs, n_chunks, n_peaks, B, P,
                               (float*)d_out, out_size / 4);

    // 2. pool: single wave, one contiguous row range per warp (multiple of 8).
    int sms = 148, dev = 0;
    cudaGetDevice(&dev);
    cudaDeviceGetAttribute(&sms, cudaDevAttrMultiProcessorCount, dev);
    const int nblk = sms * BLOCKS_PER_SM;
    const int n_warps = nblk * (THREADS / 32);
    const int rpw = ((total_rows + n_warps - 1) / n_warps + 7) & ~7;

    cudaLaunchConfig_t cfg = {};
    cfg.gridDim  = dim3(nblk, 1, 1);
    cfg.blockDim = dim3(THREADS, 1, 1);
    cfg.dynamicSmemBytes = 0;
    cfg.stream = 0;  // legacy default stream (same as <<<>>>, capture-safe)
    cudaLaunchAttribute attrs[1];
    attrs[0].id = cudaLaunchAttributeProgrammaticStreamSerialization;
    attrs[0].val.programmaticStreamSerializationAllowed = 1;
    cfg.attrs = attrs;
    cfg.numAttrs = 1;

    cudaError_t e = cudaLaunchKernelEx(&cfg, pool_kernel,
                                       x, (float*)d_out, n_chunks,
                                       total_rows, rpw);
    if (e != cudaSuccess) {
        // fallback: plain serialized launch
        pool_kernel<<<nblk, THREADS>>>(x, (float*)d_out, n_chunks,
                                       total_rows, rpw);
    }
}